// round 1
// baseline (speedup 1.0000x reference)
#include <cuda_runtime.h>
#include <cstdint>

#define RES   64
#define CH    8
#define NB    64
#define CORE  32
#define POS   16
#define DIMSZ (CORE*CORE*CORE*CH)   // 262144
#define BATCH 32

// Each thread owns a pair of adjacent dim indices (d0, d0+1).
// Accumulates all 32 batches in packed f32x2 registers so U is read exactly once.
__global__ void __launch_bounds__(256) core_subspace_kernel(
    const float* __restrict__ z,   // (32, 64)
    const float* __restrict__ U,   // (64, 262144)
    const float* __restrict__ L,   // (64,)
    const float* __restrict__ mu,  // (262144,)
    float* __restrict__ out)       // (32, 8, 64, 64, 64), pre-zeroed
{
    // zL packed as {v, v} 64-bit so inner loop is a single LDS.64 broadcast.
    __shared__ unsigned long long s_zl[BATCH * NB];  // 16 KB

    const int tid = threadIdx.x;
    for (int idx = tid; idx < BATCH * NB; idx += 256) {
        float v = L[idx & (NB - 1)] * z[idx];
        unsigned int vb = __float_as_uint(v);
        unsigned long long p;
        asm("mov.b64 %0, {%1, %1};" : "=l"(p) : "r"(vb));
        s_zl[idx] = p;
    }
    __syncthreads();

    const int t  = blockIdx.x * 256 + tid;   // 0 .. 131071
    const int d0 = t * 2;                    // even dim index

    // Initialize accumulators with mu (free "+ mu").
    const unsigned long long mu2 =
        *reinterpret_cast<const unsigned long long*>(mu + d0);

    unsigned long long acc[BATCH];
#pragma unroll
    for (int b = 0; b < BATCH; b++) acc[b] = mu2;

    const float* Up = U + d0;
#pragma unroll 4
    for (int k = 0; k < NB; k++) {
        const unsigned long long u2 =
            *reinterpret_cast<const unsigned long long*>(Up + (size_t)k * DIMSZ);
#pragma unroll
        for (int b = 0; b < BATCH; b++) {
            asm("fma.rn.f32x2 %0, %1, %2, %0;"
                : "+l"(acc[b])
                : "l"(u2), "l"(s_zl[b * NB + k]));
        }
    }

    // Scatter the dim pair into the core region.
    // dim = ((c*32 + i)*32 + j)*32 + w   (w = d0 & 31, even -> 8B aligned store)
    const int w = d0 & 31;
    const int j = (d0 >> 5) & 31;
    const int i = (d0 >> 10) & 31;
    const int c = d0 >> 15;

    const size_t obase = (size_t)c * (RES * RES * RES)
                       + (size_t)(i + POS) * (RES * RES)
                       + (size_t)(j + POS) * RES
                       + (size_t)(w + POS);

#pragma unroll
    for (int b = 0; b < BATCH; b++) {
        *reinterpret_cast<unsigned long long*>(
            out + (size_t)b * (CH * RES * RES * RES) + obase) = acc[b];
    }
}

extern "C" void kernel_launch(void* const* d_in, const int* in_sizes, int n_in,
                              void* d_out, int out_size)
{
    const float* z  = (const float*)d_in[0];
    const float* U  = (const float*)d_in[1];
    const float* L  = (const float*)d_in[2];
    const float* mu = (const float*)d_in[3];
    float* out = (float*)d_out;

    // Zero entire output (87.5% stays zero); graph-capturable memset node.
    cudaMemsetAsync(out, 0, (size_t)out_size * sizeof(float), 0);

    // 131072 dim-pairs / 256 threads = 512 blocks.
    core_subspace_kernel<<<512, 256>>>(z, U, L, mu, out);
}

// round 2
// speedup vs baseline: 1.4301x; 1.4301x over previous
#include <cuda_runtime.h>
#include <cstdint>

#define RES   64
#define CH    8
#define NB    64
#define CORE  32
#define POS   16
#define DIMSZ (CORE*CORE*CORE*CH)   // 262144
#define BATCH 32

#define COMPUTE_BLOCKS 512          // 512*256 threads * 2 dims = 262144 dims
#define F4_TOTAL  (BATCH*CH*RES*RES*RES/4)   // 16,777,216 float4
#define F4_PER_TH 8
#define ZERO_BLOCKS (F4_TOTAL / (256 * F4_PER_TH))  // 8192
#define GRID (COMPUTE_BLOCKS + ZERO_BLOCKS)

// Fused kernel:
//  blocks [0, 512):      (L*z)@U + mu, scattered into the core of out
//  blocks [512, 8704):   zero-fill the periphery (skip core region)
__global__ void __launch_bounds__(256, 2) core_subspace_fused(
    const float* __restrict__ z,   // (32, 64)
    const float* __restrict__ U,   // (64, 262144)
    const float* __restrict__ L,   // (64,)
    const float* __restrict__ mu,  // (262144,)
    float* __restrict__ out)       // (32, 8, 64, 64, 64)
{
    const int tid = threadIdx.x;

    if (blockIdx.x >= COMPUTE_BLOCKS) {
        // ---------------- periphery zero-fill ----------------
        const int zb = blockIdx.x - COMPUTE_BLOCKS;
        const float4 zero4 = make_float4(0.f, 0.f, 0.f, 0.f);
        float4* o4 = reinterpret_cast<float4*>(out);
#pragma unroll
        for (int c = 0; c < F4_PER_TH; c++) {
            const int f = zb * (256 * F4_PER_TH) + c * 256 + tid;
            // f = ((((b*8+ch)*64 + i)*64) + j)*16 + w4
            const unsigned w4 = f & 15;
            const unsigned j  = (f >> 4)  & 63;
            const unsigned i  = (f >> 10) & 63;
            const bool in_core = (i - 16u < 32u) & (j - 16u < 32u) & (w4 - 4u < 8u);
            if (!in_core) o4[f] = zero4;   // core is written by compute blocks
        }
        return;
    }

    // ---------------- GEMM + scatter ----------------
    // zL packed as pairs of duplicated f32x2: one LDS.128 feeds two FFMA2s.
    __shared__ alignas(16) unsigned long long s_zl[BATCH * NB];  // 16 KB

    for (int idx = tid; idx < BATCH * NB; idx += 256) {
        float v = L[idx & (NB - 1)] * z[idx];
        unsigned int vb = __float_as_uint(v);
        unsigned long long p;
        asm("mov.b64 %0, {%1, %1};" : "=l"(p) : "r"(vb));
        s_zl[idx] = p;
    }
    __syncthreads();

    const int t  = blockIdx.x * 256 + tid;   // 0 .. 131071
    const int d0 = t * 2;                    // even dim index

    const unsigned long long mu2 =
        *reinterpret_cast<const unsigned long long*>(mu + d0);

    unsigned long long acc[BATCH];
#pragma unroll
    for (int b = 0; b < BATCH; b++) acc[b] = mu2;

    const float* Up = U + d0;
    const ulonglong2* zl2 = reinterpret_cast<const ulonglong2*>(s_zl);

#pragma unroll 2
    for (int kp = 0; kp < NB / 2; kp++) {
        const unsigned long long u2a =
            *reinterpret_cast<const unsigned long long*>(Up + (size_t)(2 * kp)     * DIMSZ);
        const unsigned long long u2b =
            *reinterpret_cast<const unsigned long long*>(Up + (size_t)(2 * kp + 1) * DIMSZ);
#pragma unroll
        for (int b = 0; b < BATCH; b++) {
            const ulonglong2 zz = zl2[b * (NB / 2) + kp];  // LDS.128 broadcast
            asm("fma.rn.f32x2 %0, %1, %2, %0;" : "+l"(acc[b]) : "l"(u2a), "l"(zz.x));
            asm("fma.rn.f32x2 %0, %1, %2, %0;" : "+l"(acc[b]) : "l"(u2b), "l"(zz.y));
        }
    }

    // Scatter the dim pair into the core region.
    const int w = d0 & 31;
    const int j = (d0 >> 5) & 31;
    const int i = (d0 >> 10) & 31;
    const int c = d0 >> 15;

    const size_t obase = (size_t)c * (RES * RES * RES)
                       + (size_t)(i + POS) * (RES * RES)
                       + (size_t)(j + POS) * RES
                       + (size_t)(w + POS);

#pragma unroll
    for (int b = 0; b < BATCH; b++) {
        *reinterpret_cast<unsigned long long*>(
            out + (size_t)b * (CH * RES * RES * RES) + obase) = acc[b];
    }
}

extern "C" void kernel_launch(void* const* d_in, const int* in_sizes, int n_in,
                              void* d_out, int out_size)
{
    const float* z  = (const float*)d_in[0];
    const float* U  = (const float*)d_in[1];
    const float* L  = (const float*)d_in[2];
    const float* mu = (const float*)d_in[3];
    float* out = (float*)d_out;

    core_subspace_fused<<<GRID, 256>>>(z, U, L, mu, out);
}